// round 8
// baseline (speedup 1.0000x reference)
#include <cuda_runtime.h>
#include <cuda_bf16.h>
#include <cstdint>

// Problem constants (from reference setup_inputs)
#define BATCH  4096
#define CWDIM  1024
#define CODES  128     // C
#define BOOK   256     // K
#define DEMB   8       // D

#define THREADS 256
#define GROUP   512                 // rows per group (2 per thread)
#define ROWS_PB (2 * GROUP)         // 1024 rows per block

// ---------------------------------------------------------------------------
// Fused, pipelined kernel. grid = (BATCH/1024, CODES), block = 256, one c.
// Phase 0: argmin group A (2 rows/thread, LDS-lean loop).
// Phase 1: drain one_hot(A) interleaved with argmin group B (1 store : 2 k).
// Phase 2: drain one_hot(B).
// score(k) = 0.5*||c_k||^2 - x . c_k  (same argmin as full distance)
// ---------------------------------------------------------------------------
__global__ void __launch_bounds__(THREADS)
vq_fused_kernel(const float* __restrict__ x,
                const float* __restrict__ cb,
                float* __restrict__ cw_embed,
                float* __restrict__ one_hot)
{
    __shared__ float4        s_cb[BOOK * 2];    // codebook[c]: 256 x 8 floats
    __shared__ float4        s_h4[BOOK / 4];    // 0.5*||c||^2, 4 k's per float4
    __shared__ unsigned char s_idxA[GROUP];
    __shared__ unsigned char s_idxB[GROUP];

    const int c  = blockIdx.y;
    const int t  = threadIdx.x;
    const int b0 = blockIdx.x * ROWS_PB;

    // ---- Stage codebook[c] ----
    const float4* cb4 = reinterpret_cast<const float4*>(cb + (size_t)c * BOOK * DEMB);
    {
        float4 r0 = cb4[t * 2 + 0];
        float4 r1 = cb4[t * 2 + 1];
        s_cb[t * 2 + 0] = r0;
        s_cb[t * 2 + 1] = r1;
        float h = 0.5f * (r0.x * r0.x + r0.y * r0.y + r0.z * r0.z + r0.w * r0.w +
                          r1.x * r1.x + r1.y * r1.y + r1.z * r1.z + r1.w * r1.w);
        reinterpret_cast<float*>(s_h4)[t] = h;
    }

    // ---- x loads, group A rows: b0+t, b0+256+t ----
    const float4* xA0 = reinterpret_cast<const float4*>(x + (size_t)(b0 + t)       * CWDIM + c * DEMB);
    const float4* xA1 = reinterpret_cast<const float4*>(x + (size_t)(b0 + 256 + t) * CWDIM + c * DEMB);
    float4 a0 = xA0[0], a1 = xA0[1];
    float4 e0 = xA1[0], e1 = xA1[1];
    const float an0 = -a0.x, an1 = -a0.y, an2 = -a0.z, an3 = -a0.w;
    const float an4 = -a1.x, an5 = -a1.y, an6 = -a1.z, an7 = -a1.w;
    const float bn0 = -e0.x, bn1 = -e0.y, bn2 = -e0.z, bn3 = -e0.w;
    const float bn4 = -e1.x, bn5 = -e1.y, bn6 = -e1.z, bn7 = -e1.w;

    __syncthreads();

    // ======== Phase 0: argmin group A ========
    float bestA0 = 3.4e38f, bestA1 = 3.4e38f;
    int   biA0 = 0, biA1 = 0;

    #pragma unroll 2
    for (int kq = 0; kq < BOOK / 4; ++kq) {
        const float4 h4 = s_h4[kq];
        const float hh[4] = {h4.x, h4.y, h4.z, h4.w};
        #pragma unroll
        for (int j = 0; j < 4; ++j) {
            const int k = kq * 4 + j;
            float4 c0 = s_cb[2 * k + 0];
            float4 c1 = s_cb[2 * k + 1];
            float s0 = hh[j], s1 = hh[j];
            s0 = fmaf(an0, c0.x, s0);  s1 = fmaf(bn0, c0.x, s1);
            s0 = fmaf(an1, c0.y, s0);  s1 = fmaf(bn1, c0.y, s1);
            s0 = fmaf(an2, c0.z, s0);  s1 = fmaf(bn2, c0.z, s1);
            s0 = fmaf(an3, c0.w, s0);  s1 = fmaf(bn3, c0.w, s1);
            s0 = fmaf(an4, c1.x, s0);  s1 = fmaf(bn4, c1.x, s1);
            s0 = fmaf(an5, c1.y, s0);  s1 = fmaf(bn5, c1.y, s1);
            s0 = fmaf(an6, c1.z, s0);  s1 = fmaf(bn6, c1.z, s1);
            s0 = fmaf(an7, c1.w, s0);  s1 = fmaf(bn7, c1.w, s1);
            // strict < keeps FIRST minimum (matches jnp.argmin tie-break)
            if (s0 < bestA0) { bestA0 = s0; biA0 = k; }
            if (s1 < bestA1) { bestA1 = s1; biA1 = k; }
        }
    }

    s_idxA[t]       = (unsigned char)biA0;
    s_idxA[t + 256] = (unsigned char)biA1;

    // cw_embed group A
    {
        float4* o0 = reinterpret_cast<float4*>(cw_embed + (size_t)(b0 + t)       * CWDIM + c * DEMB);
        o0[0] = s_cb[2 * biA0 + 0];
        o0[1] = s_cb[2 * biA0 + 1];
        float4* o1 = reinterpret_cast<float4*>(cw_embed + (size_t)(b0 + 256 + t) * CWDIM + c * DEMB);
        o1[0] = s_cb[2 * biA1 + 0];
        o1[1] = s_cb[2 * biA1 + 1];
    }

    // ---- x loads, group B rows: b0+512+t, b0+768+t (latency hides under drain)
    const float4* xB0 = reinterpret_cast<const float4*>(x + (size_t)(b0 + 512 + t) * CWDIM + c * DEMB);
    const float4* xB1 = reinterpret_cast<const float4*>(x + (size_t)(b0 + 768 + t) * CWDIM + c * DEMB);
    float4 g0 = xB0[0], g1 = xB0[1];
    float4 f0 = xB1[0], f1 = xB1[1];
    const float cn0 = -g0.x, cn1 = -g0.y, cn2 = -g0.z, cn3 = -g0.w;
    const float cn4 = -g1.x, cn5 = -g1.y, cn6 = -g1.z, cn7 = -g1.w;
    const float dn0 = -f0.x, dn1 = -f0.y, dn2 = -f0.z, dn3 = -f0.w;
    const float dn4 = -f1.x, dn5 = -f1.y, dn6 = -f1.z, dn7 = -f1.w;

    __syncthreads();

    // ======== Phase 1: drain one_hot(A) + argmin group B (1 store : 2 k) ====
    const int off  = t & 63;      // float4 slot within a row
    const int rsub = t >> 6;      // which of 4 rows per store iter
    const unsigned kb = (unsigned)off * 4u;
    const size_t step4 = (size_t)4 * (CODES * BOOK / 4);

    float4* ohA = reinterpret_cast<float4*>(one_hot)
                + (size_t)(b0 + rsub) * (CODES * BOOK / 4)
                + (size_t)c * (BOOK / 4) + off;

    float bestB0 = 3.4e38f, bestB1 = 3.4e38f;
    int   biB0 = 0, biB1 = 0;

    #pragma unroll 4
    for (int it = 0; it < GROUP / 4; ++it) {            // 128 iterations
        // one coalesced value store for group A
        {
            const unsigned idx = s_idxA[it * 4 + rsub];
            float4 v;
            v.x = (idx == kb + 0u) ? 1.0f : 0.0f;
            v.y = (idx == kb + 1u) ? 1.0f : 0.0f;
            v.z = (idx == kb + 2u) ? 1.0f : 0.0f;
            v.w = (idx == kb + 3u) ? 1.0f : 0.0f;
            *ohA = v;
            ohA += step4;
        }
        // two k-steps of group B argmin
        {
            const int kq = it >> 1;
            const float4 h4 = s_h4[kq];
            const float hpair[2] = { (it & 1) ? h4.z : h4.x,
                                     (it & 1) ? h4.w : h4.y };
            #pragma unroll
            for (int j = 0; j < 2; ++j) {
                const int k = it * 2 + j;
                float4 c0 = s_cb[2 * k + 0];
                float4 c1 = s_cb[2 * k + 1];
                float s0 = hpair[j], s1 = hpair[j];
                s0 = fmaf(cn0, c0.x, s0);  s1 = fmaf(dn0, c0.x, s1);
                s0 = fmaf(cn1, c0.y, s0);  s1 = fmaf(dn1, c0.y, s1);
                s0 = fmaf(cn2, c0.z, s0);  s1 = fmaf(dn2, c0.z, s1);
                s0 = fmaf(cn3, c0.w, s0);  s1 = fmaf(dn3, c0.w, s1);
                s0 = fmaf(cn4, c1.x, s0);  s1 = fmaf(dn4, c1.x, s1);
                s0 = fmaf(cn5, c1.y, s0);  s1 = fmaf(dn5, c1.y, s1);
                s0 = fmaf(cn6, c1.z, s0);  s1 = fmaf(dn6, c1.z, s1);
                s0 = fmaf(cn7, c1.w, s0);  s1 = fmaf(dn7, c1.w, s1);
                if (s0 < bestB0) { bestB0 = s0; biB0 = k; }
                if (s1 < bestB1) { bestB1 = s1; biB1 = k; }
            }
        }
    }

    s_idxB[t]       = (unsigned char)biB0;
    s_idxB[t + 256] = (unsigned char)biB1;

    // cw_embed group B
    {
        float4* o0 = reinterpret_cast<float4*>(cw_embed + (size_t)(b0 + 512 + t) * CWDIM + c * DEMB);
        o0[0] = s_cb[2 * biB0 + 0];
        o0[1] = s_cb[2 * biB0 + 1];
        float4* o1 = reinterpret_cast<float4*>(cw_embed + (size_t)(b0 + 768 + t) * CWDIM + c * DEMB);
        o1[0] = s_cb[2 * biB1 + 0];
        o1[1] = s_cb[2 * biB1 + 1];
    }

    __syncthreads();

    // ======== Phase 2: drain one_hot(B) ========
    float4* ohB = reinterpret_cast<float4*>(one_hot)
                + (size_t)(b0 + 512 + rsub) * (CODES * BOOK / 4)
                + (size_t)c * (BOOK / 4) + off;

    #pragma unroll 8
    for (int it = 0; it < GROUP / 4; ++it) {            // 128 iterations
        const unsigned idx = s_idxB[it * 4 + rsub];
        float4 v;
        v.x = (idx == kb + 0u) ? 1.0f : 0.0f;
        v.y = (idx == kb + 1u) ? 1.0f : 0.0f;
        v.z = (idx == kb + 2u) ? 1.0f : 0.0f;
        v.w = (idx == kb + 3u) ? 1.0f : 0.0f;
        *ohB = v;
        ohB += step4;
    }
}

// ---------------------------------------------------------------------------
extern "C" void kernel_launch(void* const* d_in, const int* in_sizes, int n_in,
                              void* d_out, int out_size)
{
    const float* x  = (const float*)d_in[0];   // [4096, 1024]
    const float* cb = (const float*)d_in[1];   // [128, 256, 8]

    float* cw_embed = (float*)d_out;                               // [4096, 1024]
    float* one_hot  = (float*)d_out + (size_t)BATCH * CWDIM;       // [4096, 128, 256]

    dim3 grid(BATCH / ROWS_PB, CODES);                             // (4, 128)
    vq_fused_kernel<<<grid, THREADS>>>(x, cb, cw_embed, one_hot);
}